// round 8
// baseline (speedup 1.0000x reference)
#include <cuda_runtime.h>
#include <cuda_fp16.h>
#include <math.h>

#define Wdim 14
#define Bdim 64
#define Cdim 256
#define WB   896          // W*B
#define HW   196          // H*W
#define NEGS 64
#define EPSF 1e-11f
#define FULL_ROWS 12544   // 14*14*64
#define TOT_ROWS  29568   // 10752+9856+8960

// per-k constants (kk = 0,1,2)
#define ROWS0 10752
#define ROWS1 9856
#define ROWS2 8960
#define MB0 84            // rows/128
#define MB1 77
#define MB2 70
#define DB0 1344          // rows/8
#define DB1 1232
#define DB2 1120
#define DBT (DB0 + DB1 + DB2)   // 3696

// Scratch (no cudaMalloc allowed)
__device__ float    g_zt  [FULL_ROWS * Cdim];  // tf32-rounded z
__device__ __half   g_ctxh[FULL_ROWS * Cdim];  // fp16 ctx
__device__ __half   g_flat[TOT_ROWS * Cdim];   // fp16 GEMM output, all k concat
__device__ float    g_partial[4096];
__device__ unsigned g_count = 0;

__device__ __forceinline__ float tf32_round(float x) {
    float r;
    asm("cvt.rna.tf32.f32 %0, %1;" : "=f"(r) : "f"(x));
    return r;
}

// ---------------------------------------------------------------------------
// Coalesced transpose. Block = (which, b, 32-wide c-tile): 1024 blocks, 25KB smem.
// Read: 32 c-rows x 196 floats via float4 (fully coalesced).
// smem tile [32][197] -> bank stride 5 (gcd(5,32)=1) => conflict-free reads.
// Write: dst[(hw*64+b)*256 + ct + cc], warp covers 32 consecutive cc.
// ---------------------------------------------------------------------------
__global__ void __launch_bounds__(256) transpose_kernel(const float* __restrict__ z,
                                                        const float* __restrict__ cin)
{
    __shared__ float s[32][197];
    int which = blockIdx.x >> 9;             // 0: z -> g_zt, 1: c -> g_ctxh
    int bi = blockIdx.x & 511;
    int b  = bi >> 3;
    int ct = (bi & 7) * 32;
    const float4* sp = (const float4*)((which ? cin : z)
                                       + (size_t)b * (Cdim * HW) + (size_t)ct * HW);
    int t = threadIdx.x;
    for (int i = t; i < 32 * 49; i += 256) {
        int c = i / 49, q = i % 49;
        float4 v = sp[(size_t)c * 49 + q];
        s[c][q * 4 + 0] = v.x;
        s[c][q * 4 + 1] = v.y;
        s[c][q * 4 + 2] = v.z;
        s[c][q * 4 + 3] = v.w;
    }
    __syncthreads();
    if (which) {
        for (int i = t; i < HW * 32; i += 256) {
            int hw = i >> 5, cc = i & 31;
            g_ctxh[(size_t)(hw * Bdim + b) * Cdim + ct + cc] = __float2half_rn(s[cc][hw]);
        }
    } else {
        for (int i = t; i < HW * 32; i += 256) {
            int hw = i >> 5, cc = i & 31;
            g_zt[(size_t)(hw * Bdim + b) * Cdim + ct + cc] = tf32_round(s[cc][hw]);
        }
    }
}

// ---------------------------------------------------------------------------
// Fused tf32 GEMM, all 3 k's. grid = (231, 4). BM=128, BN=64, BK=32, pipelined.
// ---------------------------------------------------------------------------
__device__ __forceinline__ void mma_tf32(float c[4], const unsigned a[4], const unsigned b[2])
{
    asm volatile(
        "mma.sync.aligned.m16n8k8.row.col.f32.tf32.tf32.f32 "
        "{%0,%1,%2,%3}, {%4,%5,%6,%7}, {%8,%9}, {%0,%1,%2,%3};\n"
        : "+f"(c[0]), "+f"(c[1]), "+f"(c[2]), "+f"(c[3])
        : "r"(a[0]), "r"(a[1]), "r"(a[2]), "r"(a[3]), "r"(b[0]), "r"(b[1]));
}

__global__ void __launch_bounds__(256) gemm_tf32_kernel(const float* __restrict__ Wk)
{
    __shared__ float As[128 * 32];
    __shared__ float Bs[32 * 64];

    int bx = blockIdx.x;
    int kk, mb;
    if (bx < MB0)            { kk = 0; mb = bx; }
    else if (bx < MB0 + MB1) { kk = 1; mb = bx - MB0; }
    else                     { kk = 2; mb = bx - MB0 - MB1; }

    const float* A  = g_zt + (size_t)(kk + 2) * WB * Cdim;
    const float* Wm = Wk + (size_t)kk * Cdim * Cdim;
    __half* F = g_flat + (size_t)(kk == 0 ? 0 : (kk == 1 ? ROWS0 : ROWS0 + ROWS1)) * Cdim;

    int t = threadIdx.x;
    int lane = t & 31;
    int w = t >> 5;
    int warp_m = w & 3;
    int warp_n = w >> 2;
    int rowBase = mb * 128;
    int colBase = blockIdx.y * 64;

    float acc[2][4][4];
    #pragma unroll
    for (int i = 0; i < 2; i++)
        #pragma unroll
        for (int j = 0; j < 4; j++)
            #pragma unroll
            for (int e = 0; e < 4; e++) acc[i][j][e] = 0.f;

    float4 ra[4], rb[2];
    #pragma unroll
    for (int p = 0; p < 4; p++) {
        int idx = p * 256 + t;
        int r = idx >> 3, cq = idx & 7;
        ra[p] = *(const float4*)(A + (size_t)(rowBase + r) * Cdim + cq * 4);
    }
    #pragma unroll
    for (int q = 0; q < 2; q++) {
        int idx = q * 256 + t;
        int n = idx & 63, kq = idx >> 6;
        rb[q] = *(const float4*)(Wm + (size_t)(colBase + n) * Cdim + kq * 4);
    }

    for (int k0 = 0; k0 < Cdim; k0 += 32) {
        #pragma unroll
        for (int p = 0; p < 4; p++) {
            int idx = p * 256 + t;
            int r = idx >> 3, cq = idx & 7;
            *(float4*)(As + r * 32 + ((cq ^ (r & 7)) << 2)) = ra[p];
        }
        #pragma unroll
        for (int q = 0; q < 2; q++) {
            int idx = q * 256 + t;
            int n = idx & 63, kq = idx >> 6;
            int kb = kq * 4;
            Bs[(kb + 0) * 64 + (n ^ 0)]  = tf32_round(rb[q].x);
            Bs[(kb + 1) * 64 + (n ^ 8)]  = tf32_round(rb[q].y);
            Bs[(kb + 2) * 64 + (n ^ 16)] = tf32_round(rb[q].z);
            Bs[(kb + 3) * 64 + (n ^ 24)] = tf32_round(rb[q].w);
        }
        __syncthreads();

        if (k0 + 32 < Cdim) {
            #pragma unroll
            for (int p = 0; p < 4; p++) {
                int idx = p * 256 + t;
                int r = idx >> 3, cq = idx & 7;
                ra[p] = *(const float4*)(A + (size_t)(rowBase + r) * Cdim + k0 + 32 + cq * 4);
            }
            #pragma unroll
            for (int q = 0; q < 2; q++) {
                int idx = q * 256 + t;
                int n = idx & 63, kq = idx >> 6;
                rb[q] = *(const float4*)(Wm + (size_t)(colBase + n) * Cdim + k0 + 32 + kq * 4);
            }
        }

        #pragma unroll
        for (int kt = 0; kt < 4; kt++) {
            unsigned a[2][4];
            int cA = kt * 8 + (lane & 3);
            #pragma unroll
            for (int i = 0; i < 2; i++) {
                int r0 = warp_m * 32 + i * 16 + (lane >> 2);
                int r1 = r0 + 8;
                a[i][0] = __float_as_uint(As[r0 * 32 + ( cA      ^ (4 * (r0 & 7)))]);
                a[i][1] = __float_as_uint(As[r1 * 32 + ( cA      ^ (4 * (r1 & 7)))]);
                a[i][2] = __float_as_uint(As[r0 * 32 + ((cA + 4) ^ (4 * (r0 & 7)))]);
                a[i][3] = __float_as_uint(As[r1 * 32 + ((cA + 4) ^ (4 * (r1 & 7)))]);
            }
            unsigned b[4][2];
            int kB = kt * 8 + (lane & 3);
            int sw = 8 * (kB & 3);
            #pragma unroll
            for (int j = 0; j < 4; j++) {
                int n = warp_n * 32 + j * 8 + (lane >> 2);
                b[j][0] = __float_as_uint(Bs[ kB      * 64 + (n ^ sw)]);
                b[j][1] = __float_as_uint(Bs[(kB + 4) * 64 + (n ^ sw)]);
            }
            #pragma unroll
            for (int i = 0; i < 2; i++)
                #pragma unroll
                for (int j = 0; j < 4; j++)
                    mma_tf32(acc[i][j], a[i], b[j]);
        }
        __syncthreads();
    }

    #pragma unroll
    for (int i = 0; i < 2; i++) {
        #pragma unroll
        for (int j = 0; j < 4; j++) {
            int row = rowBase + warp_m * 32 + i * 16 + (lane >> 2);
            int col = colBase + warp_n * 32 + j * 8 + 2 * (lane & 3);
            *(__half2*)(F + (size_t)row * Cdim + col) =
                __floats2half2_rn(acc[i][j][0], acc[i][j][1]);
            *(__half2*)(F + (size_t)(row + 8) * Cdim + col) =
                __floats2half2_rn(acc[i][j][2], acc[i][j][3]);
        }
    }
}

// ---------------------------------------------------------------------------
// Fused dot kernel (staged P[32] butterfly for max MLP) + last-block finalize.
// __launch_bounds__(256, 5): cap regs at 51 so the finalize path cannot
// drop occupancy below 5 CTAs/SM (spills, if any, land on the 1-block path).
// ---------------------------------------------------------------------------
__global__ void __launch_bounds__(256, 5) dot_kernel(const int* __restrict__ n1,
                                                     const int* __restrict__ n2,
                                                     const int* __restrict__ n3,
                                                     float* __restrict__ out)
{
    int bx = blockIdx.x;
    int kk, lb;
    if (bx < DB0)            { kk = 0; lb = bx; }
    else if (bx < DB0 + DB1) { kk = 1; lb = bx - DB0; }
    else                     { kk = 2; lb = bx - DB0 - DB1; }
    const int* nidx = kk == 0 ? n1 : (kk == 1 ? n2 : n3);
    float wscale = kk == 0 ? (1.0f / (3.0f * ROWS0))
                 : (kk == 1 ? (1.0f / (3.0f * ROWS1)) : (1.0f / (3.0f * ROWS2)));
    int flatOfs  = kk == 0 ? 0 : (kk == 1 ? ROWS0 : ROWS0 + ROWS1);

    int warp = threadIdx.x >> 5;
    int lane = threadIdx.x & 31;
    int r = lb * 8 + warp;

    uint4 cv = *(const uint4*)(g_ctxh + (size_t)r * Cdim + lane * 8);
    __half2 c0 = *(__half2*)&cv.x;
    __half2 c1 = *(__half2*)&cv.y;
    __half2 c2 = *(__half2*)&cv.z;
    __half2 c3 = *(__half2*)&cv.w;

    const __half* fbase = g_flat + (size_t)flatOfs * Cdim + lane * 8;

    auto partial = [&](int j) -> float {
        uint4 v = *(const uint4*)(fbase + (size_t)j * Cdim);
        __half2 acc = __hmul2(*(__half2*)&v.x, c0);
        acc = __hfma2(*(__half2*)&v.y, c1, acc);
        acc = __hfma2(*(__half2*)&v.z, c2, acc);
        acc = __hfma2(*(__half2*)&v.w, c3, acc);
        float2 f = __half22float2(acc);
        return f.x + f.y;
    };

    float m = partial(r);
    #pragma unroll
    for (int off = 16; off; off >>= 1)
        m += __shfl_xor_sync(0xffffffffu, m, off);

    int i0 = nidx[r * NEGS + lane];
    int i1 = nidx[r * NEGS + 32 + lane];

    float P[32];

    // ---- group A: negs 0..31 (all 32 gathers back-to-back: max MLP) ----
    #pragma unroll
    for (int n = 0; n < 32; n++)
        P[n] = partial(__shfl_sync(0xffffffffu, i0, n));
    #pragma unroll
    for (int b = 16; b; b >>= 1) {
        #pragma unroll
        for (int j = 0; j < b; j++) {
            bool up = (lane & b) != 0;
            float keep = up ? P[j + b] : P[j];
            float send = up ? P[j] : P[j + b];
            P[j] = keep + __shfl_xor_sync(0xffffffffu, send, b);
        }
    }
    float l0 = P[0];

    // ---- group B: negs 32..63 ----
    #pragma unroll
    for (int n = 0; n < 32; n++)
        P[n] = partial(__shfl_sync(0xffffffffu, i1, n));
    #pragma unroll
    for (int b = 16; b; b >>= 1) {
        #pragma unroll
        for (int j = 0; j < b; j++) {
            bool up = (lane & b) != 0;
            float keep = up ? P[j + b] : P[j];
            float send = up ? P[j] : P[j + b];
            P[j] = keep + __shfl_xor_sync(0xffffffffu, send, b);
        }
    }
    float l1 = P[0];

    // softmax over [m, l0(32), l1(32)]
    float mx = fmaxf(m, fmaxf(l0, l1));
    #pragma unroll
    for (int off = 16; off; off >>= 1)
        mx = fmaxf(mx, __shfl_xor_sync(0xffffffffu, mx, off));
    float se = __expf(l0 - mx) + __expf(l1 - mx);
    #pragma unroll
    for (int off = 16; off; off >>= 1)
        se += __shfl_xor_sync(0xffffffffu, se, off);
    float em = __expf(m - mx);
    se += em;
    float loss = -__logf(em / se + EPSF);

    __shared__ float sacc[8];
    __shared__ bool  s_last;
    if (lane == 0) sacc[warp] = loss * wscale;
    __syncthreads();
    if (threadIdx.x == 0) {
        float s = 0.f;
        #pragma unroll
        for (int i = 0; i < 8; i++) s += sacc[i];
        __stcg(&g_partial[bx], s);
        __threadfence();
        unsigned prev = atomicAdd(&g_count, 1u);
        s_last = (prev == DBT - 1);
    }
    __syncthreads();

    // deterministic last-block finalize (fixed-order tree)
    if (s_last) {
        __shared__ float sred[256];
        float acc = 0.f;
        for (int i = threadIdx.x; i < DBT; i += 256) acc += __ldcg(&g_partial[i]);
        sred[threadIdx.x] = acc;
        __syncthreads();
        for (int st = 128; st; st >>= 1) {
            if (threadIdx.x < st) sred[threadIdx.x] += sred[threadIdx.x + st];
            __syncthreads();
        }
        if (threadIdx.x == 0) {
            out[0] = sred[0];
            g_count = 0;           // reset for next graph replay
        }
    }
}

// ---------------------------------------------------------------------------
extern "C" void kernel_launch(void* const* d_in, const int* in_sizes, int n_in,
                              void* d_out, int out_size)
{
    const float* z   = (const float*)d_in[0];
    const float* cin = (const float*)d_in[1];
    const float* Wk  = (const float*)d_in[2];
    float* out = (float*)d_out;

    transpose_kernel<<<1024, 256>>>(z, cin);
    gemm_tf32_kernel<<<dim3(MB0 + MB1 + MB2, Cdim / 64), 256>>>(Wk);
    dot_kernel<<<DBT, 256>>>((const int*)d_in[3], (const int*)d_in[4],
                             (const int*)d_in[5], out);
}

// round 12
// speedup vs baseline: 1.0681x; 1.0681x over previous
#include <cuda_runtime.h>
#include <cuda_fp16.h>
#include <math.h>

#define Wdim 14
#define Bdim 64
#define Cdim 256
#define WB   896          // W*B
#define HW   196          // H*W
#define NEGS 64
#define EPSF 1e-11f
#define FULL_ROWS 12544   // 14*14*64
#define TOT_ROWS  29568   // 10752+9856+8960

// per-k constants (kk = 0,1,2)
#define ROWS0 10752
#define ROWS1 9856
#define ROWS2 8960
#define MB0 84            // rows/128
#define MB1 77
#define MB2 70
#define DB0 1344          // rows/8
#define DB1 1232
#define DB2 1120
#define DBT (DB0 + DB1 + DB2)   // 3696

// Scratch (no cudaMalloc allowed)
__device__ float    g_zt  [FULL_ROWS * Cdim];  // tf32-rounded z
__device__ __half   g_ctxh[FULL_ROWS * Cdim];  // fp16 ctx
__device__ __half   g_flat[TOT_ROWS * Cdim];   // fp16 GEMM output, all k concat
__device__ float    g_partial[4096];

__device__ __forceinline__ float tf32_round(float x) {
    float r;
    asm("cvt.rna.tf32.f32 %0, %1;" : "=f"(r) : "f"(x));
    return r;
}

// ---------------------------------------------------------------------------
// Coalesced transpose (R8 version, measured 10.8us).
// Block = (which, b, 32-wide c-tile): 1024 blocks, 25KB smem.
// ---------------------------------------------------------------------------
__global__ void __launch_bounds__(256) transpose_kernel(const float* __restrict__ z,
                                                        const float* __restrict__ cin)
{
    __shared__ float s[32][197];
    int which = blockIdx.x >> 9;             // 0: z -> g_zt, 1: c -> g_ctxh
    int bi = blockIdx.x & 511;
    int b  = bi >> 3;
    int ct = (bi & 7) * 32;
    const float4* sp = (const float4*)((which ? cin : z)
                                       + (size_t)b * (Cdim * HW) + (size_t)ct * HW);
    int t = threadIdx.x;
    for (int i = t; i < 32 * 49; i += 256) {
        int c = i / 49, q = i % 49;
        float4 v = sp[(size_t)c * 49 + q];
        s[c][q * 4 + 0] = v.x;
        s[c][q * 4 + 1] = v.y;
        s[c][q * 4 + 2] = v.z;
        s[c][q * 4 + 3] = v.w;
    }
    __syncthreads();
    if (which) {
        for (int i = t; i < HW * 32; i += 256) {
            int hw = i >> 5, cc = i & 31;
            g_ctxh[(size_t)(hw * Bdim + b) * Cdim + ct + cc] = __float2half_rn(s[cc][hw]);
        }
    } else {
        for (int i = t; i < HW * 32; i += 256) {
            int hw = i >> 5, cc = i & 31;
            g_zt[(size_t)(hw * Bdim + b) * Cdim + ct + cc] = tf32_round(s[cc][hw]);
        }
    }
}

// ---------------------------------------------------------------------------
// Fused tf32 GEMM, all 3 k's. grid = (231, 4). BM=128, BN=64, BK=32, pipelined.
// ---------------------------------------------------------------------------
__device__ __forceinline__ void mma_tf32(float c[4], const unsigned a[4], const unsigned b[2])
{
    asm volatile(
        "mma.sync.aligned.m16n8k8.row.col.f32.tf32.tf32.f32 "
        "{%0,%1,%2,%3}, {%4,%5,%6,%7}, {%8,%9}, {%0,%1,%2,%3};\n"
        : "+f"(c[0]), "+f"(c[1]), "+f"(c[2]), "+f"(c[3])
        : "r"(a[0]), "r"(a[1]), "r"(a[2]), "r"(a[3]), "r"(b[0]), "r"(b[1]));
}

__global__ void __launch_bounds__(256) gemm_tf32_kernel(const float* __restrict__ Wk)
{
    __shared__ float As[128 * 32];
    __shared__ float Bs[32 * 64];

    int bx = blockIdx.x;
    int kk, mb;
    if (bx < MB0)            { kk = 0; mb = bx; }
    else if (bx < MB0 + MB1) { kk = 1; mb = bx - MB0; }
    else                     { kk = 2; mb = bx - MB0 - MB1; }

    const float* A  = g_zt + (size_t)(kk + 2) * WB * Cdim;
    const float* Wm = Wk + (size_t)kk * Cdim * Cdim;
    __half* F = g_flat + (size_t)(kk == 0 ? 0 : (kk == 1 ? ROWS0 : ROWS0 + ROWS1)) * Cdim;

    int t = threadIdx.x;
    int lane = t & 31;
    int w = t >> 5;
    int warp_m = w & 3;
    int warp_n = w >> 2;
    int rowBase = mb * 128;
    int colBase = blockIdx.y * 64;

    float acc[2][4][4];
    #pragma unroll
    for (int i = 0; i < 2; i++)
        #pragma unroll
        for (int j = 0; j < 4; j++)
            #pragma unroll
            for (int e = 0; e < 4; e++) acc[i][j][e] = 0.f;

    float4 ra[4], rb[2];
    #pragma unroll
    for (int p = 0; p < 4; p++) {
        int idx = p * 256 + t;
        int r = idx >> 3, cq = idx & 7;
        ra[p] = *(const float4*)(A + (size_t)(rowBase + r) * Cdim + cq * 4);
    }
    #pragma unroll
    for (int q = 0; q < 2; q++) {
        int idx = q * 256 + t;
        int n = idx & 63, kq = idx >> 6;
        rb[q] = *(const float4*)(Wm + (size_t)(colBase + n) * Cdim + kq * 4);
    }

    for (int k0 = 0; k0 < Cdim; k0 += 32) {
        #pragma unroll
        for (int p = 0; p < 4; p++) {
            int idx = p * 256 + t;
            int r = idx >> 3, cq = idx & 7;
            *(float4*)(As + r * 32 + ((cq ^ (r & 7)) << 2)) = ra[p];
        }
        #pragma unroll
        for (int q = 0; q < 2; q++) {
            int idx = q * 256 + t;
            int n = idx & 63, kq = idx >> 6;
            int kb = kq * 4;
            Bs[(kb + 0) * 64 + (n ^ 0)]  = tf32_round(rb[q].x);
            Bs[(kb + 1) * 64 + (n ^ 8)]  = tf32_round(rb[q].y);
            Bs[(kb + 2) * 64 + (n ^ 16)] = tf32_round(rb[q].z);
            Bs[(kb + 3) * 64 + (n ^ 24)] = tf32_round(rb[q].w);
        }
        __syncthreads();

        if (k0 + 32 < Cdim) {
            #pragma unroll
            for (int p = 0; p < 4; p++) {
                int idx = p * 256 + t;
                int r = idx >> 3, cq = idx & 7;
                ra[p] = *(const float4*)(A + (size_t)(rowBase + r) * Cdim + k0 + 32 + cq * 4);
            }
            #pragma unroll
            for (int q = 0; q < 2; q++) {
                int idx = q * 256 + t;
                int n = idx & 63, kq = idx >> 6;
                rb[q] = *(const float4*)(Wm + (size_t)(colBase + n) * Cdim + k0 + 32 + kq * 4);
            }
        }

        #pragma unroll
        for (int kt = 0; kt < 4; kt++) {
            unsigned a[2][4];
            int cA = kt * 8 + (lane & 3);
            #pragma unroll
            for (int i = 0; i < 2; i++) {
                int r0 = warp_m * 32 + i * 16 + (lane >> 2);
                int r1 = r0 + 8;
                a[i][0] = __float_as_uint(As[r0 * 32 + ( cA      ^ (4 * (r0 & 7)))]);
                a[i][1] = __float_as_uint(As[r1 * 32 + ( cA      ^ (4 * (r1 & 7)))]);
                a[i][2] = __float_as_uint(As[r0 * 32 + ((cA + 4) ^ (4 * (r0 & 7)))]);
                a[i][3] = __float_as_uint(As[r1 * 32 + ((cA + 4) ^ (4 * (r1 & 7)))]);
            }
            unsigned b[4][2];
            int kB = kt * 8 + (lane & 3);
            int sw = 8 * (kB & 3);
            #pragma unroll
            for (int j = 0; j < 4; j++) {
                int n = warp_n * 32 + j * 8 + (lane >> 2);
                b[j][0] = __float_as_uint(Bs[ kB      * 64 + (n ^ sw)]);
                b[j][1] = __float_as_uint(Bs[(kB + 4) * 64 + (n ^ sw)]);
            }
            #pragma unroll
            for (int i = 0; i < 2; i++)
                #pragma unroll
                for (int j = 0; j < 4; j++)
                    mma_tf32(acc[i][j], a[i], b[j]);
        }
        __syncthreads();
    }

    #pragma unroll
    for (int i = 0; i < 2; i++) {
        #pragma unroll
        for (int j = 0; j < 4; j++) {
            int row = rowBase + warp_m * 32 + i * 16 + (lane >> 2);
            int col = colBase + warp_n * 32 + j * 8 + 2 * (lane & 3);
            *(__half2*)(F + (size_t)row * Cdim + col) =
                __floats2half2_rn(acc[i][j][0], acc[i][j][1]);
            *(__half2*)(F + (size_t)(row + 8) * Cdim + col) =
                __floats2half2_rn(acc[i][j][2], acc[i][j][3]);
        }
    }
}

// ---------------------------------------------------------------------------
// Fused dot kernel — exact R5 version (staged P[32] butterfly, no finalize).
// ---------------------------------------------------------------------------
__global__ void __launch_bounds__(256) dot_kernel(const int* __restrict__ n1,
                                                  const int* __restrict__ n2,
                                                  const int* __restrict__ n3)
{
    int bx = blockIdx.x;
    int kk, lb;
    if (bx < DB0)            { kk = 0; lb = bx; }
    else if (bx < DB0 + DB1) { kk = 1; lb = bx - DB0; }
    else                     { kk = 2; lb = bx - DB0 - DB1; }
    const int* nidx = kk == 0 ? n1 : (kk == 1 ? n2 : n3);
    float wscale = kk == 0 ? (1.0f / (3.0f * ROWS0))
                 : (kk == 1 ? (1.0f / (3.0f * ROWS1)) : (1.0f / (3.0f * ROWS2)));
    int flatOfs  = kk == 0 ? 0 : (kk == 1 ? ROWS0 : ROWS0 + ROWS1);

    int warp = threadIdx.x >> 5;
    int lane = threadIdx.x & 31;
    int r = lb * 8 + warp;

    uint4 cv = *(const uint4*)(g_ctxh + (size_t)r * Cdim + lane * 8);
    __half2 c0 = *(__half2*)&cv.x;
    __half2 c1 = *(__half2*)&cv.y;
    __half2 c2 = *(__half2*)&cv.z;
    __half2 c3 = *(__half2*)&cv.w;

    const __half* fbase = g_flat + (size_t)flatOfs * Cdim + lane * 8;

    auto partial = [&](int j) -> float {
        uint4 v = *(const uint4*)(fbase + (size_t)j * Cdim);
        __half2 acc = __hmul2(*(__half2*)&v.x, c0);
        acc = __hfma2(*(__half2*)&v.y, c1, acc);
        acc = __hfma2(*(__half2*)&v.z, c2, acc);
        acc = __hfma2(*(__half2*)&v.w, c3, acc);
        float2 f = __half22float2(acc);
        return f.x + f.y;
    };

    float m = partial(r);
    #pragma unroll
    for (int off = 16; off; off >>= 1)
        m += __shfl_xor_sync(0xffffffffu, m, off);

    int i0 = nidx[r * NEGS + lane];
    int i1 = nidx[r * NEGS + 32 + lane];

    float P[32];

    // ---- group A: negs 0..31 (all 32 gathers back-to-back: max MLP) ----
    #pragma unroll
    for (int n = 0; n < 32; n++)
        P[n] = partial(__shfl_sync(0xffffffffu, i0, n));
    #pragma unroll
    for (int b = 16; b; b >>= 1) {
        #pragma unroll
        for (int j = 0; j < b; j++) {
            bool up = (lane & b) != 0;
            float keep = up ? P[j + b] : P[j];
            float send = up ? P[j] : P[j + b];
            P[j] = keep + __shfl_xor_sync(0xffffffffu, send, b);
        }
    }
    float l0 = P[0];

    // ---- group B: negs 32..63 ----
    #pragma unroll
    for (int n = 0; n < 32; n++)
        P[n] = partial(__shfl_sync(0xffffffffu, i1, n));
    #pragma unroll
    for (int b = 16; b; b >>= 1) {
        #pragma unroll
        for (int j = 0; j < b; j++) {
            bool up = (lane & b) != 0;
            float keep = up ? P[j + b] : P[j];
            float send = up ? P[j] : P[j + b];
            P[j] = keep + __shfl_xor_sync(0xffffffffu, send, b);
        }
    }
    float l1 = P[0];

    // softmax over [m, l0(32), l1(32)]
    float mx = fmaxf(m, fmaxf(l0, l1));
    #pragma unroll
    for (int off = 16; off; off >>= 1)
        mx = fmaxf(mx, __shfl_xor_sync(0xffffffffu, mx, off));
    float se = __expf(l0 - mx) + __expf(l1 - mx);
    #pragma unroll
    for (int off = 16; off; off >>= 1)
        se += __shfl_xor_sync(0xffffffffu, se, off);
    float em = __expf(m - mx);
    se += em;
    float loss = -__logf(em / se + EPSF);

    __shared__ float sacc[8];
    if (lane == 0) sacc[warp] = loss * wscale;
    __syncthreads();
    if (threadIdx.x == 0) {
        float s = 0.f;
        #pragma unroll
        for (int i = 0; i < 8; i++) s += sacc[i];
        g_partial[bx] = s;
    }
}

// Deterministic final reduction (separate launch — measured cheaper than folding)
__global__ void finalize_kernel(int n, float* __restrict__ out)
{
    __shared__ float s[256];
    float acc = 0.f;
    for (int i = threadIdx.x; i < n; i += 256) acc += g_partial[i];
    s[threadIdx.x] = acc;
    __syncthreads();
    for (int st = 128; st; st >>= 1) {
        if (threadIdx.x < st) s[threadIdx.x] += s[threadIdx.x + st];
        __syncthreads();
    }
    if (threadIdx.x == 0) out[0] = s[0];
}

// ---------------------------------------------------------------------------
extern "C" void kernel_launch(void* const* d_in, const int* in_sizes, int n_in,
                              void* d_out, int out_size)
{
    const float* z   = (const float*)d_in[0];
    const float* cin = (const float*)d_in[1];
    const float* Wk  = (const float*)d_in[2];
    float* out = (float*)d_out;

    transpose_kernel<<<1024, 256>>>(z, cin);
    gemm_tf32_kernel<<<dim3(MB0 + MB1 + MB2, Cdim / 64), 256>>>(Wk);
    dot_kernel<<<DBT, 256>>>((const int*)d_in[3], (const int*)d_in[4],
                             (const int*)d_in[5]);
    finalize_kernel<<<1, 256>>>(DBT, out);
}

// round 13
// speedup vs baseline: 1.2129x; 1.1355x over previous
#include <cuda_runtime.h>
#include <cuda_fp16.h>
#include <math.h>

#define Wdim 14
#define Bdim 64
#define Cdim 256
#define WB   896          // W*B
#define HW   196          // H*W
#define NEGS 64
#define EPSF 1e-11f
#define FULL_ROWS 12544   // 14*14*64
#define TOT_ROWS  29568   // 10752+9856+8960

// per-k constants (kk = 0,1,2)
#define ROWS0 10752
#define ROWS1 9856
#define ROWS2 8960
#define MB0 84            // rows/128
#define MB1 77
#define MB2 70
#define DB0 1344          // rows/8
#define DB1 1232
#define DB2 1120
#define DBT (DB0 + DB1 + DB2)   // 3696

// Scratch (no cudaMalloc allowed)
__device__ __half   g_zth [FULL_ROWS * Cdim];  // fp16 z (GEMM A)
__device__ __half   g_ctxh[FULL_ROWS * Cdim];  // fp16 ctx
__device__ __half   g_flat[TOT_ROWS * Cdim];   // fp16 GEMM output, all k concat
__device__ float    g_partial[4096];

// ---------------------------------------------------------------------------
// Coalesced transpose. Block = (which, b, 32-wide c-tile): 1024 blocks.
// Both outputs now fp16.
// ---------------------------------------------------------------------------
__global__ void __launch_bounds__(256) transpose_kernel(const float* __restrict__ z,
                                                        const float* __restrict__ cin)
{
    __shared__ float s[32][197];
    int which = blockIdx.x >> 9;             // 0: z -> g_zth, 1: c -> g_ctxh
    int bi = blockIdx.x & 511;
    int b  = bi >> 3;
    int ct = (bi & 7) * 32;
    const float4* sp = (const float4*)((which ? cin : z)
                                       + (size_t)b * (Cdim * HW) + (size_t)ct * HW);
    int t = threadIdx.x;
    for (int i = t; i < 32 * 49; i += 256) {
        int c = i / 49, q = i % 49;
        float4 v = sp[(size_t)c * 49 + q];
        s[c][q * 4 + 0] = v.x;
        s[c][q * 4 + 1] = v.y;
        s[c][q * 4 + 2] = v.z;
        s[c][q * 4 + 3] = v.w;
    }
    __syncthreads();
    __half* dst = which ? g_ctxh : g_zth;
    for (int i = t; i < HW * 32; i += 256) {
        int hw = i >> 5, cc = i & 31;
        dst[(size_t)(hw * Bdim + b) * Cdim + ct + cc] = __float2half_rn(s[cc][hw]);
    }
}

// ---------------------------------------------------------------------------
// Fused fp16 GEMM (mma.sync.m16n8k16), all 3 k's. grid = (231, 4).
// BM=128, BN=64, BK=32 (2 x k16 steps), register-prefetch pipeline.
// A smem: pair-word p at r*16 + (p ^ (((r>>1)&3)*4))    [8 KB]
// B smem: pair-row k>>1, word at (k>>1)*64 + (n ^ (((k>>1)&3)*8))  [4 KB]
// ---------------------------------------------------------------------------
__device__ __forceinline__ void mma_f16(float c[4], const unsigned a[4], const unsigned b[2])
{
    asm volatile(
        "mma.sync.aligned.m16n8k16.row.col.f32.f16.f16.f32 "
        "{%0,%1,%2,%3}, {%4,%5,%6,%7}, {%8,%9}, {%0,%1,%2,%3};\n"
        : "+f"(c[0]), "+f"(c[1]), "+f"(c[2]), "+f"(c[3])
        : "r"(a[0]), "r"(a[1]), "r"(a[2]), "r"(a[3]), "r"(b[0]), "r"(b[1]));
}

__global__ void __launch_bounds__(256) gemm_f16_kernel(const float* __restrict__ Wk)
{
    __shared__ unsigned AsW[128 * 16];   // 8 KB
    __shared__ unsigned BsW[16 * 64];    // 4 KB

    int bx = blockIdx.x;
    int kk, mb;
    if (bx < MB0)            { kk = 0; mb = bx; }
    else if (bx < MB0 + MB1) { kk = 1; mb = bx - MB0; }
    else                     { kk = 2; mb = bx - MB0 - MB1; }

    const __half* A  = g_zth + (size_t)(kk + 2) * WB * Cdim;
    const float*  Wm = Wk + (size_t)kk * Cdim * Cdim;
    __half* F = g_flat + (size_t)(kk == 0 ? 0 : (kk == 1 ? ROWS0 : ROWS0 + ROWS1)) * Cdim;

    int t = threadIdx.x;
    int lane = t & 31;
    int w = t >> 5;
    int warp_m = w & 3;
    int warp_n = w >> 2;
    int rowBase = mb * 128;
    int colBase = blockIdx.y * 64;

    float acc[2][4][4];
    #pragma unroll
    for (int i = 0; i < 2; i++)
        #pragma unroll
        for (int j = 0; j < 4; j++)
            #pragma unroll
            for (int e = 0; e < 4; e++) acc[i][j][e] = 0.f;

    uint4  ra[2];
    float4 rbf[2];
    // prefetch k0 = 0
    #pragma unroll
    for (int p = 0; p < 2; p++) {
        int idx = p * 256 + t;
        int r = idx >> 2, q = idx & 3;
        ra[p] = *(const uint4*)(A + (size_t)(rowBase + r) * Cdim + q * 8);
    }
    #pragma unroll
    for (int p = 0; p < 2; p++) {
        int idx = p * 256 + t;
        int n = idx & 63, kq = idx >> 6;   // kq 0..7 across both passes
        rbf[p] = *(const float4*)(Wm + (size_t)(colBase + n) * Cdim + kq * 4);
    }

    for (int k0 = 0; k0 < Cdim; k0 += 32) {
        // store A tile (uint4 = 4 pair-words; (quad*4 + w)^s == (quad*4^s)+w since s in bits 2-3)
        #pragma unroll
        for (int p = 0; p < 2; p++) {
            int idx = p * 256 + t;
            int r = idx >> 2, q = idx & 3;
            int sA = ((r >> 1) & 3) * 4;
            *(uint4*)(AsW + r * 16 + ((q * 4) ^ sA)) = ra[p];
        }
        // store B tile (2 pair-words per float4)
        #pragma unroll
        for (int p = 0; p < 2; p++) {
            int idx = p * 256 + t;
            int n = idx & 63, kq = idx >> 6;
            int pr = kq * 2;
            __half2 h01 = __floats2half2_rn(rbf[p].x, rbf[p].y);
            __half2 h23 = __floats2half2_rn(rbf[p].z, rbf[p].w);
            BsW[ pr      * 64 + (n ^ (( pr      & 3) * 8))] = *(unsigned*)&h01;
            BsW[(pr + 1) * 64 + (n ^ (((pr + 1) & 3) * 8))] = *(unsigned*)&h23;
        }
        __syncthreads();

        if (k0 + 32 < Cdim) {
            #pragma unroll
            for (int p = 0; p < 2; p++) {
                int idx = p * 256 + t;
                int r = idx >> 2, q = idx & 3;
                ra[p] = *(const uint4*)(A + (size_t)(rowBase + r) * Cdim + k0 + 32 + q * 8);
            }
            #pragma unroll
            for (int p = 0; p < 2; p++) {
                int idx = p * 256 + t;
                int n = idx & 63, kq = idx >> 6;
                rbf[p] = *(const float4*)(Wm + (size_t)(colBase + n) * Cdim + k0 + 32 + kq * 4);
            }
        }

        #pragma unroll
        for (int kt = 0; kt < 2; kt++) {
            int q = lane & 3;
            unsigned a[2][4];
            int p0 = kt * 8 + q;
            #pragma unroll
            for (int i = 0; i < 2; i++) {
                int r0 = warp_m * 32 + i * 16 + (lane >> 2);
                int r1 = r0 + 8;
                int s0 = ((r0 >> 1) & 3) * 4;
                int s1 = ((r1 >> 1) & 3) * 4;
                a[i][0] = AsW[r0 * 16 + ( p0      ^ s0)];
                a[i][1] = AsW[r1 * 16 + ( p0      ^ s1)];
                a[i][2] = AsW[r0 * 16 + ((p0 + 4) ^ s0)];
                a[i][3] = AsW[r1 * 16 + ((p0 + 4) ^ s1)];
            }
            unsigned b[4][2];
            int prb = kt * 8 + q;
            int sb  = q * 8;
            #pragma unroll
            for (int j = 0; j < 4; j++) {
                int n = warp_n * 32 + j * 8 + (lane >> 2);
                b[j][0] = BsW[ prb      * 64 + (n ^ sb)];
                b[j][1] = BsW[(prb + 4) * 64 + (n ^ sb)];
            }
            #pragma unroll
            for (int i = 0; i < 2; i++)
                #pragma unroll
                for (int j = 0; j < 4; j++)
                    mma_f16(acc[i][j], a[i], b[j]);
        }
        __syncthreads();
    }

    #pragma unroll
    for (int i = 0; i < 2; i++) {
        #pragma unroll
        for (int j = 0; j < 4; j++) {
            int row = rowBase + warp_m * 32 + i * 16 + (lane >> 2);
            int col = colBase + warp_n * 32 + j * 8 + 2 * (lane & 3);
            *(__half2*)(F + (size_t)row * Cdim + col) =
                __floats2half2_rn(acc[i][j][0], acc[i][j][1]);
            *(__half2*)(F + (size_t)(row + 8) * Cdim + col) =
                __floats2half2_rn(acc[i][j][2], acc[i][j][3]);
        }
    }
}

// ---------------------------------------------------------------------------
// Fused dot kernel (staged P[32] butterfly) — L2-bandwidth bound, unchanged.
// ---------------------------------------------------------------------------
__global__ void __launch_bounds__(256) dot_kernel(const int* __restrict__ n1,
                                                  const int* __restrict__ n2,
                                                  const int* __restrict__ n3)
{
    int bx = blockIdx.x;
    int kk, lb;
    if (bx < DB0)            { kk = 0; lb = bx; }
    else if (bx < DB0 + DB1) { kk = 1; lb = bx - DB0; }
    else                     { kk = 2; lb = bx - DB0 - DB1; }
    const int* nidx = kk == 0 ? n1 : (kk == 1 ? n2 : n3);
    float wscale = kk == 0 ? (1.0f / (3.0f * ROWS0))
                 : (kk == 1 ? (1.0f / (3.0f * ROWS1)) : (1.0f / (3.0f * ROWS2)));
    int flatOfs  = kk == 0 ? 0 : (kk == 1 ? ROWS0 : ROWS0 + ROWS1);

    int warp = threadIdx.x >> 5;
    int lane = threadIdx.x & 31;
    int r = lb * 8 + warp;

    uint4 cv = *(const uint4*)(g_ctxh + (size_t)r * Cdim + lane * 8);
    __half2 c0 = *(__half2*)&cv.x;
    __half2 c1 = *(__half2*)&cv.y;
    __half2 c2 = *(__half2*)&cv.z;
    __half2 c3 = *(__half2*)&cv.w;

    const __half* fbase = g_flat + (size_t)flatOfs * Cdim + lane * 8;

    auto partial = [&](int j) -> float {
        uint4 v = *(const uint4*)(fbase + (size_t)j * Cdim);
        __half2 acc = __hmul2(*(__half2*)&v.x, c0);
        acc = __hfma2(*(__half2*)&v.y, c1, acc);
        acc = __hfma2(*(__half2*)&v.z, c2, acc);
        acc = __hfma2(*(__half2*)&v.w, c3, acc);
        float2 f = __half22float2(acc);
        return f.x + f.y;
    };

    float m = partial(r);
    #pragma unroll
    for (int off = 16; off; off >>= 1)
        m += __shfl_xor_sync(0xffffffffu, m, off);

    int i0 = nidx[r * NEGS + lane];
    int i1 = nidx[r * NEGS + 32 + lane];

    float P[32];

    #pragma unroll
    for (int n = 0; n < 32; n++)
        P[n] = partial(__shfl_sync(0xffffffffu, i0, n));
    #pragma unroll
    for (int b = 16; b; b >>= 1) {
        #pragma unroll
        for (int j = 0; j < b; j++) {
            bool up = (lane & b) != 0;
            float keep = up ? P[j + b] : P[j];
            float send = up ? P[j] : P[j + b];
            P[j] = keep + __shfl_xor_sync(0xffffffffu, send, b);
        }
    }
    float l0 = P[0];

    #pragma unroll
    for (int n = 0; n < 32; n++)
        P[n] = partial(__shfl_sync(0xffffffffu, i1, n));
    #pragma unroll
    for (int b = 16; b; b >>= 1) {
        #pragma unroll
        for (int j = 0; j < b; j++) {
            bool up = (lane & b) != 0;
            float keep = up ? P[j + b] : P[j];
            float send = up ? P[j] : P[j + b];
            P[j] = keep + __shfl_xor_sync(0xffffffffu, send, b);
        }
    }
    float l1 = P[0];

    float mx = fmaxf(m, fmaxf(l0, l1));
    #pragma unroll
    for (int off = 16; off; off >>= 1)
        mx = fmaxf(mx, __shfl_xor_sync(0xffffffffu, mx, off));
    float se = __expf(l0 - mx) + __expf(l1 - mx);
    #pragma unroll
    for (int off = 16; off; off >>= 1)
        se += __shfl_xor_sync(0xffffffffu, se, off);
    float em = __expf(m - mx);
    se += em;
    float loss = -__logf(em / se + EPSF);

    __shared__ float sacc[8];
    if (lane == 0) sacc[warp] = loss * wscale;
    __syncthreads();
    if (threadIdx.x == 0) {
        float s = 0.f;
        #pragma unroll
        for (int i = 0; i < 8; i++) s += sacc[i];
        g_partial[bx] = s;
    }
}

// Deterministic final reduction (separate launch — measured cheaper than folding)
__global__ void finalize_kernel(int n, float* __restrict__ out)
{
    __shared__ float s[256];
    float acc = 0.f;
    for (int i = threadIdx.x; i < n; i += 256) acc += g_partial[i];
    s[threadIdx.x] = acc;
    __syncthreads();
    for (int st = 128; st; st >>= 1) {
        if (threadIdx.x < st) s[threadIdx.x] += s[threadIdx.x + st];
        __syncthreads();
    }
    if (threadIdx.x == 0) out[0] = s[0];
}

// ---------------------------------------------------------------------------
extern "C" void kernel_launch(void* const* d_in, const int* in_sizes, int n_in,
                              void* d_out, int out_size)
{
    const float* z   = (const float*)d_in[0];
    const float* cin = (const float*)d_in[1];
    const float* Wk  = (const float*)d_in[2];
    float* out = (float*)d_out;

    transpose_kernel<<<1024, 256>>>(z, cin);
    gemm_f16_kernel<<<dim3(MB0 + MB1 + MB2, Cdim / 64), 256>>>(Wk);
    dot_kernel<<<DBT, 256>>>((const int*)d_in[3], (const int*)d_in[4],
                             (const int*)d_in[5]);
    finalize_kernel<<<1, 256>>>(DBT, out);
}

// round 16
// speedup vs baseline: 1.2237x; 1.0089x over previous
#include <cuda_runtime.h>
#include <cuda_fp16.h>
#include <math.h>

#define Wdim 14
#define Bdim 64
#define Cdim 256
#define WB   896          // W*B
#define HW   196          // H*W
#define NEGS 64
#define EPSF 1e-11f
#define FULL_ROWS 12544   // 14*14*64
#define TOT_ROWS  29568   // 10752+9856+8960

// per-k constants (kk = 0,1,2)
#define ROWS0 10752
#define ROWS1 9856
#define ROWS2 8960
#define MB0 84            // rows/128
#define MB1 77
#define MB2 70
#define DB0 1344          // rows/8
#define DB1 1232
#define DB2 1120
#define DBT (DB0 + DB1 + DB2)   // 3696

// Scratch (no cudaMalloc allowed)
__device__ __half   g_zth [FULL_ROWS * Cdim];  // fp16 z (GEMM A)
__device__ __half   g_ctxh[FULL_ROWS * Cdim];  // fp16 ctx
__device__ __half   g_flat[TOT_ROWS * Cdim];   // fp16 GEMM output, all k concat
__device__ float    g_partial[4096];

// ---------------------------------------------------------------------------
// Coalesced transpose. Block = (which, b, 32-wide c-tile): 1024 blocks.
// Writes vectorized as __half2 (pairs of adjacent channels).
// ---------------------------------------------------------------------------
__global__ void __launch_bounds__(256) transpose_kernel(const float* __restrict__ z,
                                                        const float* __restrict__ cin)
{
    __shared__ float s[32][197];
    int which = blockIdx.x >> 9;             // 0: z -> g_zth, 1: c -> g_ctxh
    int bi = blockIdx.x & 511;
    int b  = bi >> 3;
    int ct = (bi & 7) * 32;
    const float4* sp = (const float4*)((which ? cin : z)
                                       + (size_t)b * (Cdim * HW) + (size_t)ct * HW);
    int t = threadIdx.x;
    for (int i = t; i < 32 * 49; i += 256) {
        int c = i / 49, q = i % 49;
        float4 v = sp[(size_t)c * 49 + q];
        s[c][q * 4 + 0] = v.x;
        s[c][q * 4 + 1] = v.y;
        s[c][q * 4 + 2] = v.z;
        s[c][q * 4 + 3] = v.w;
    }
    __syncthreads();
    __half* dst = which ? g_ctxh : g_zth;
    for (int i = t; i < HW * 16; i += 256) {
        int hw = i >> 4, p = i & 15;
        __half2 v = __floats2half2_rn(s[2 * p][hw], s[2 * p + 1][hw]);
        *(__half2*)(dst + (size_t)(hw * Bdim + b) * Cdim + ct + 2 * p) = v;
    }
}

// ---------------------------------------------------------------------------
// Fused fp16 GEMM (mma.sync.m16n8k16), all 3 k's. grid = (231, 4).
// BM=128, BN=64, BK=32 (2 x k16 steps), register-prefetch pipeline.
// (R13 version, verified: 13us, rel_err 4.49e-6)
// A smem: pair-word p at r*16 + (p ^ (((r>>1)&3)*4))    [8 KB]
// B smem: pair-row k>>1, word at (k>>1)*64 + (n ^ (((k>>1)&3)*8))  [4 KB]
// ---------------------------------------------------------------------------
__device__ __forceinline__ void mma_f16(float c[4], const unsigned a[4], const unsigned b[2])
{
    asm volatile(
        "mma.sync.aligned.m16n8k16.row.col.f32.f16.f16.f32 "
        "{%0,%1,%2,%3}, {%4,%5,%6,%7}, {%8,%9}, {%0,%1,%2,%3};\n"
        : "+f"(c[0]), "+f"(c[1]), "+f"(c[2]), "+f"(c[3])
        : "r"(a[0]), "r"(a[1]), "r"(a[2]), "r"(a[3]), "r"(b[0]), "r"(b[1]));
}

__global__ void __launch_bounds__(256) gemm_f16_kernel(const float* __restrict__ Wk)
{
    __shared__ unsigned AsW[128 * 16];   // 8 KB
    __shared__ unsigned BsW[16 * 64];    // 4 KB

    int bx = blockIdx.x;
    int kk, mb;
    if (bx < MB0)            { kk = 0; mb = bx; }
    else if (bx < MB0 + MB1) { kk = 1; mb = bx - MB0; }
    else                     { kk = 2; mb = bx - MB0 - MB1; }

    const __half* A  = g_zth + (size_t)(kk + 2) * WB * Cdim;
    const float*  Wm = Wk + (size_t)kk * Cdim * Cdim;
    __half* F = g_flat + (size_t)(kk == 0 ? 0 : (kk == 1 ? ROWS0 : ROWS0 + ROWS1)) * Cdim;

    int t = threadIdx.x;
    int lane = t & 31;
    int w = t >> 5;
    int warp_m = w & 3;
    int warp_n = w >> 2;
    int rowBase = mb * 128;
    int colBase = blockIdx.y * 64;

    float acc[2][4][4];
    #pragma unroll
    for (int i = 0; i < 2; i++)
        #pragma unroll
        for (int j = 0; j < 4; j++)
            #pragma unroll
            for (int e = 0; e < 4; e++) acc[i][j][e] = 0.f;

    uint4  ra[2];
    float4 rbf[2];
    // prefetch k0 = 0
    #pragma unroll
    for (int p = 0; p < 2; p++) {
        int idx = p * 256 + t;
        int r = idx >> 2, q = idx & 3;
        ra[p] = *(const uint4*)(A + (size_t)(rowBase + r) * Cdim + q * 8);
    }
    #pragma unroll
    for (int p = 0; p < 2; p++) {
        int idx = p * 256 + t;
        int n = idx & 63, kq = idx >> 6;
        rbf[p] = *(const float4*)(Wm + (size_t)(colBase + n) * Cdim + kq * 4);
    }

    for (int k0 = 0; k0 < Cdim; k0 += 32) {
        // store A tile (uint4 = 4 pair-words; swizzle bits 2-3 keep 4-word groups contiguous)
        #pragma unroll
        for (int p = 0; p < 2; p++) {
            int idx = p * 256 + t;
            int r = idx >> 2, q = idx & 3;
            int sA = ((r >> 1) & 3) * 4;
            *(uint4*)(AsW + r * 16 + ((q * 4) ^ sA)) = ra[p];
        }
        // store B tile (2 pair-words per float4)
        #pragma unroll
        for (int p = 0; p < 2; p++) {
            int idx = p * 256 + t;
            int n = idx & 63, kq = idx >> 6;
            int pr = kq * 2;
            __half2 h01 = __floats2half2_rn(rbf[p].x, rbf[p].y);
            __half2 h23 = __floats2half2_rn(rbf[p].z, rbf[p].w);
            BsW[ pr      * 64 + (n ^ (( pr      & 3) * 8))] = *(unsigned*)&h01;
            BsW[(pr + 1) * 64 + (n ^ (((pr + 1) & 3) * 8))] = *(unsigned*)&h23;
        }
        __syncthreads();

        if (k0 + 32 < Cdim) {
            #pragma unroll
            for (int p = 0; p < 2; p++) {
                int idx = p * 256 + t;
                int r = idx >> 2, q = idx & 3;
                ra[p] = *(const uint4*)(A + (size_t)(rowBase + r) * Cdim + k0 + 32 + q * 8);
            }
            #pragma unroll
            for (int p = 0; p < 2; p++) {
                int idx = p * 256 + t;
                int n = idx & 63, kq = idx >> 6;
                rbf[p] = *(const float4*)(Wm + (size_t)(colBase + n) * Cdim + k0 + 32 + kq * 4);
            }
        }

        #pragma unroll
        for (int kt = 0; kt < 2; kt++) {
            int q = lane & 3;
            unsigned a[2][4];
            int p0 = kt * 8 + q;
            #pragma unroll
            for (int i = 0; i < 2; i++) {
                int r0 = warp_m * 32 + i * 16 + (lane >> 2);
                int r1 = r0 + 8;
                int s0 = ((r0 >> 1) & 3) * 4;
                int s1 = ((r1 >> 1) & 3) * 4;
                a[i][0] = AsW[r0 * 16 + ( p0      ^ s0)];
                a[i][1] = AsW[r1 * 16 + ( p0      ^ s1)];
                a[i][2] = AsW[r0 * 16 + ((p0 + 4) ^ s0)];
                a[i][3] = AsW[r1 * 16 + ((p0 + 4) ^ s1)];
            }
            unsigned b[4][2];
            int prb = kt * 8 + q;
            int sb  = q * 8;
            #pragma unroll
            for (int j = 0; j < 4; j++) {
                int n = warp_n * 32 + j * 8 + (lane >> 2);
                b[j][0] = BsW[ prb      * 64 + (n ^ sb)];
                b[j][1] = BsW[(prb + 4) * 64 + (n ^ sb)];
            }
            #pragma unroll
            for (int i = 0; i < 2; i++)
                #pragma unroll
                for (int j = 0; j < 4; j++)
                    mma_f16(acc[i][j], a[i], b[j]);
        }
        __syncthreads();
    }

    #pragma unroll
    for (int i = 0; i < 2; i++) {
        #pragma unroll
        for (int j = 0; j < 4; j++) {
            int row = rowBase + warp_m * 32 + i * 16 + (lane >> 2);
            int col = colBase + warp_n * 32 + j * 8 + 2 * (lane & 3);
            *(__half2*)(F + (size_t)row * Cdim + col) =
                __floats2half2_rn(acc[i][j][0], acc[i][j][1]);
            *(__half2*)(F + (size_t)(row + 8) * Cdim + col) =
                __floats2half2_rn(acc[i][j][2], acc[i][j][3]);
        }
    }
}

// ---------------------------------------------------------------------------
// Fused dot kernel (staged P[32] butterfly) — at L2 roofline, unchanged.
// ---------------------------------------------------------------------------
__global__ void __launch_bounds__(256) dot_kernel(const int* __restrict__ n1,
                                                  const int* __restrict__ n2,
                                                  const int* __restrict__ n3)
{
    int bx = blockIdx.x;
    int kk, lb;
    if (bx < DB0)            { kk = 0; lb = bx; }
    else if (bx < DB0 + DB1) { kk = 1; lb = bx - DB0; }
    else                     { kk = 2; lb = bx - DB0 - DB1; }
    const int* nidx = kk == 0 ? n1 : (kk == 1 ? n2 : n3);
    float wscale = kk == 0 ? (1.0f / (3.0f * ROWS0))
                 : (kk == 1 ? (1.0f / (3.0f * ROWS1)) : (1.0f / (3.0f * ROWS2)));
    int flatOfs  = kk == 0 ? 0 : (kk == 1 ? ROWS0 : ROWS0 + ROWS1);

    int warp = threadIdx.x >> 5;
    int lane = threadIdx.x & 31;
    int r = lb * 8 + warp;

    uint4 cv = *(const uint4*)(g_ctxh + (size_t)r * Cdim + lane * 8);
    __half2 c0 = *(__half2*)&cv.x;
    __half2 c1 = *(__half2*)&cv.y;
    __half2 c2 = *(__half2*)&cv.z;
    __half2 c3 = *(__half2*)&cv.w;

    const __half* fbase = g_flat + (size_t)flatOfs * Cdim + lane * 8;

    auto partial = [&](int j) -> float {
        uint4 v = *(const uint4*)(fbase + (size_t)j * Cdim);
        __half2 acc = __hmul2(*(__half2*)&v.x, c0);
        acc = __hfma2(*(__half2*)&v.y, c1, acc);
        acc = __hfma2(*(__half2*)&v.z, c2, acc);
        acc = __hfma2(*(__half2*)&v.w, c3, acc);
        float2 f = __half22float2(acc);
        return f.x + f.y;
    };

    float m = partial(r);
    #pragma unroll
    for (int off = 16; off; off >>= 1)
        m += __shfl_xor_sync(0xffffffffu, m, off);

    int i0 = nidx[r * NEGS + lane];
    int i1 = nidx[r * NEGS + 32 + lane];

    float P[32];

    #pragma unroll
    for (int n = 0; n < 32; n++)
        P[n] = partial(__shfl_sync(0xffffffffu, i0, n));
    #pragma unroll
    for (int b = 16; b; b >>= 1) {
        #pragma unroll
        for (int j = 0; j < b; j++) {
            bool up = (lane & b) != 0;
            float keep = up ? P[j + b] : P[j];
            float send = up ? P[j] : P[j + b];
            P[j] = keep + __shfl_xor_sync(0xffffffffu, send, b);
        }
    }
    float l0 = P[0];

    #pragma unroll
    for (int n = 0; n < 32; n++)
        P[n] = partial(__shfl_sync(0xffffffffu, i1, n));
    #pragma unroll
    for (int b = 16; b; b >>= 1) {
        #pragma unroll
        for (int j = 0; j < b; j++) {
            bool up = (lane & b) != 0;
            float keep = up ? P[j + b] : P[j];
            float send = up ? P[j] : P[j + b];
            P[j] = keep + __shfl_xor_sync(0xffffffffu, send, b);
        }
    }
    float l1 = P[0];

    float mx = fmaxf(m, fmaxf(l0, l1));
    #pragma unroll
    for (int off = 16; off; off >>= 1)
        mx = fmaxf(mx, __shfl_xor_sync(0xffffffffu, mx, off));
    float se = __expf(l0 - mx) + __expf(l1 - mx);
    #pragma unroll
    for (int off = 16; off; off >>= 1)
        se += __shfl_xor_sync(0xffffffffu, se, off);
    float em = __expf(m - mx);
    se += em;
    float loss = -__logf(em / se + EPSF);

    __shared__ float sacc[8];
    if (lane == 0) sacc[warp] = loss * wscale;
    __syncthreads();
    if (threadIdx.x == 0) {
        float s = 0.f;
        #pragma unroll
        for (int i = 0; i < 8; i++) s += sacc[i];
        g_partial[bx] = s;
    }
}

// Deterministic final reduction (float4 loads; fixed-order tree)
__global__ void finalize_kernel(float* __restrict__ out)
{
    __shared__ float s[256];
    float acc = 0.f;
    for (int i = threadIdx.x; i < DBT / 4; i += 256) {
        float4 v = *(const float4*)(g_partial + i * 4);
        acc += (v.x + v.y) + (v.z + v.w);
    }
    s[threadIdx.x] = acc;
    __syncthreads();
    for (int st = 128; st; st >>= 1) {
        if (threadIdx.x < st) s[threadIdx.x] += s[threadIdx.x + st];
        __syncthreads();
    }
    if (threadIdx.x == 0) out[0] = s[0];
}

// ---------------------------------------------------------------------------
extern "C" void kernel_launch(void* const* d_in, const int* in_sizes, int n_in,
                              void* d_out, int out_size)
{
    const float* z   = (const float*)d_in[0];
    const float* cin = (const float*)d_in[1];
    const float* Wk  = (const float*)d_in[2];
    float* out = (float*)d_out;

    transpose_kernel<<<1024, 256>>>(z, cin);
    gemm_f16_kernel<<<dim3(MB0 + MB1 + MB2, Cdim / 64), 256>>>(Wk);
    dot_kernel<<<DBT, 256>>>((const int*)d_in[3], (const int*)d_in[4],
                             (const int*)d_in[5]);
    finalize_kernel<<<1, 256>>>(out);
}